// round 2
// baseline (speedup 1.0000x reference)
#include <cuda_runtime.h>

#define E_MAX 20000
#define FD 128
#define H1D 64
#define H2D 32
#define DD 16
#define LN_EPS 1e-5f

// Scratch: precomputed A = ef@W1[:128] + b1, B = ef@W1[128:]
__device__ float g_A[E_MAX * H1D];
__device__ float g_B[E_MAX * H1D];

// ---------------------------------------------------------------------------
// Precompute per-edge partial layer-1 outputs. blockDim = (64, 4): 4 edges per
// block, one thread per (edge, output-channel).
// ---------------------------------------------------------------------------
__global__ void precompute_kernel(const float* __restrict__ ef,
                                  const float* __restrict__ W1,
                                  const float* __restrict__ b1,
                                  int E) {
    __shared__ float efs[4][FD];
    const int tx = threadIdx.x;          // output channel 0..63
    const int ty = threadIdx.y;          // local edge 0..3
    const int tid = ty * 64 + tx;
    const int e0 = blockIdx.x * 4;

    for (int idx = tid; idx < 4 * FD; idx += 256) {
        int le = idx >> 7;
        int k  = idx & (FD - 1);
        int e  = e0 + le;
        efs[le][k] = (e < E) ? ef[e * FD + k] : 0.f;
    }
    __syncthreads();

    const int e = e0 + ty;
    if (e >= E) return;

    float a = b1[tx];
    float b = 0.f;
#pragma unroll 8
    for (int k = 0; k < FD; ++k) {
        float s = efs[ty][k];
        a = fmaf(s, W1[k * H1D + tx], a);
        b = fmaf(s, W1[(FD + k) * H1D + tx], b);
    }
    g_A[e * H1D + tx] = a;
    g_B[e * H1D + tx] = b;
}

// ---------------------------------------------------------------------------
// Main kernel: one thread per pair. Gather A[i]+B[j] -> LN -> ReLU ->
// W2 matvec -> LN -> ReLU -> W3 matvec -> stage diag in smem ->
// cooperative fully-coalesced streaming stores of the [16,16] diag-embed.
// ---------------------------------------------------------------------------
__global__ void __launch_bounds__(256)
pairs_kernel(const int* __restrict__ pi, const int* __restrict__ pj,
             const float* __restrict__ g1, const float* __restrict__ be1,
             const float* __restrict__ W2, const float* __restrict__ b2,
             const float* __restrict__ g2, const float* __restrict__ be2,
             const float* __restrict__ W3, const float* __restrict__ b3,
             float* __restrict__ out, int P) {
    __shared__ float W2s[H1D * H2D];     // 8 KB
    __shared__ float W3s[H2D * DD];      // 2 KB
    __shared__ float g1s[H1D], be1s[H1D];
    __shared__ float b2s[H2D], g2s[H2D], be2s[H2D], b3s[DD];
    __shared__ float diag[256][DD];      // 16 KB

    const int tid = threadIdx.x;

    for (int idx = tid; idx < H1D * H2D; idx += 256) W2s[idx] = W2[idx];
    for (int idx = tid; idx < H2D * DD; idx += 256) W3s[idx] = W3[idx];
    if (tid < H1D) { g1s[tid] = g1[tid]; be1s[tid] = be1[tid]; }
    if (tid < H2D) { b2s[tid] = b2[tid]; g2s[tid] = g2[tid]; be2s[tid] = be2[tid]; }
    if (tid < DD)  { b3s[tid] = b3[tid]; }
    __syncthreads();

    const int p = blockIdx.x * 256 + tid;
    float pr[DD];

    if (p < P) {
        const int i = pi[p];
        const int j = pj[p];
        float h1[H1D];
        const float4* a4 = reinterpret_cast<const float4*>(g_A + (size_t)i * H1D);
        const float4* b4 = reinterpret_cast<const float4*>(g_B + (size_t)j * H1D);
#pragma unroll
        for (int q = 0; q < H1D / 4; ++q) {
            float4 av = a4[q];
            float4 bv = b4[q];
            h1[4 * q + 0] = av.x + bv.x;
            h1[4 * q + 1] = av.y + bv.y;
            h1[4 * q + 2] = av.z + bv.z;
            h1[4 * q + 3] = av.w + bv.w;
        }
        // LayerNorm over 64 + affine + ReLU
        float mu = 0.f;
#pragma unroll
        for (int k = 0; k < H1D; ++k) mu += h1[k];
        mu *= (1.f / H1D);
        float var = 0.f;
#pragma unroll
        for (int k = 0; k < H1D; ++k) { float d = h1[k] - mu; var = fmaf(d, d, var); }
        var *= (1.f / H1D);
        float inv = rsqrtf(var + LN_EPS);
#pragma unroll
        for (int k = 0; k < H1D; ++k) {
            float v = fmaf((h1[k] - mu) * inv, g1s[k], be1s[k]);
            h1[k] = fmaxf(v, 0.f);
        }
        // Layer 2: [64] x [64,32]
        float h2[H2D];
#pragma unroll
        for (int o = 0; o < H2D; ++o) h2[o] = b2s[o];
#pragma unroll
        for (int k = 0; k < H1D; ++k) {
            float t = h1[k];
#pragma unroll
            for (int o = 0; o < H2D; ++o) h2[o] = fmaf(t, W2s[k * H2D + o], h2[o]);
        }
        // LayerNorm over 32 + affine + ReLU
        float mu2 = 0.f;
#pragma unroll
        for (int k = 0; k < H2D; ++k) mu2 += h2[k];
        mu2 *= (1.f / H2D);
        float var2 = 0.f;
#pragma unroll
        for (int k = 0; k < H2D; ++k) { float d = h2[k] - mu2; var2 = fmaf(d, d, var2); }
        var2 *= (1.f / H2D);
        float inv2 = rsqrtf(var2 + LN_EPS);
#pragma unroll
        for (int k = 0; k < H2D; ++k) {
            float v = fmaf((h2[k] - mu2) * inv2, g2s[k], be2s[k]);
            h2[k] = fmaxf(v, 0.f);
        }
        // Layer 3: [32] x [32,16]
#pragma unroll
        for (int o = 0; o < DD; ++o) pr[o] = b3s[o];
#pragma unroll
        for (int k = 0; k < H2D; ++k) {
            float t = h2[k];
#pragma unroll
            for (int o = 0; o < DD; ++o) pr[o] = fmaf(t, W3s[k * DD + o], pr[o]);
        }
    } else {
#pragma unroll
        for (int o = 0; o < DD; ++o) pr[o] = 0.f;
    }

#pragma unroll
    for (int o = 0; o < DD; ++o) diag[tid][o] = pr[o];
    __syncthreads();

    // Cooperative coalesced store of the diag-embedded [256 pairs, 16, 16] tile.
    // Per pair: 256 floats = 64 float4. Block covers 256*64 = 16384 float4.
    const size_t blockBase4 = (size_t)blockIdx.x * (256 * 64);
    const size_t total4 = (size_t)P * 64;
    float4* o4 = reinterpret_cast<float4*>(out);
#pragma unroll 4
    for (int it = 0; it < 64; ++it) {
        const int local4 = it * 256 + tid;           // 0..16383
        const size_t f4 = blockBase4 + local4;
        if (f4 < total4) {
            const int lp = local4 >> 6;              // local pair (64 float4 each)
            const int w4 = local4 & 63;              // float4 index within pair
            const int row = w4 >> 2;                 // 4 float4 per 16-float row
            const int col0 = (w4 & 3) * 4;
            float4 v = make_float4(0.f, 0.f, 0.f, 0.f);
            const int d = row - col0;
            if (d >= 0 && d < 4) {
                reinterpret_cast<float*>(&v)[d] = diag[lp][row];
            }
            __stcs(o4 + f4, v);
        }
    }
}

extern "C" void kernel_launch(void* const* d_in, const int* in_sizes, int n_in,
                              void* d_out, int out_size) {
    const float* ef  = (const float*)d_in[0];
    const int*   pi  = (const int*)d_in[1];
    const int*   pj  = (const int*)d_in[2];
    const float* W1  = (const float*)d_in[3];
    const float* b1  = (const float*)d_in[4];
    const float* g1  = (const float*)d_in[5];
    const float* be1 = (const float*)d_in[6];
    const float* W2  = (const float*)d_in[7];
    const float* b2  = (const float*)d_in[8];
    const float* g2  = (const float*)d_in[9];
    const float* be2 = (const float*)d_in[10];
    const float* W3  = (const float*)d_in[11];
    const float* b3  = (const float*)d_in[12];
    float* out = (float*)d_out;

    const int E = in_sizes[0] / FD;
    const int P = in_sizes[1];

    dim3 pb(64, 4);
    precompute_kernel<<<(E + 3) / 4, pb>>>(ef, W1, b1, E);

    const int blocks = (P + 255) / 256;
    pairs_kernel<<<blocks, 256>>>(pi, pj, g1, be1, W2, b2, g2, be2, W3, b3, out, P);
}

// round 3
// speedup vs baseline: 1.0963x; 1.0963x over previous
#include <cuda_runtime.h>
#include <cuda_fp16.h>

#define E_MAX 20000
#define FD 128
#define H1D 64
#define H2D 32
#define DD 16
#define LN_EPS 1e-5f

// Scratch: precomputed A = ef@W1[:128] + b1, B = ef@W1[128:]
__device__ float g_A[E_MAX * H1D];
__device__ float g_B[E_MAX * H1D];

// ---------------------------------------------------------------------------
// Precompute per-edge partial layer-1 outputs.
// blockDim = (32, 8): 8 edges per block, each thread owns 2 output channels.
// ---------------------------------------------------------------------------
__global__ void precompute_kernel(const float* __restrict__ ef,
                                  const float* __restrict__ W1,
                                  const float* __restrict__ b1,
                                  int E) {
    __shared__ float efs[8][FD];
    const int tx = threadIdx.x;          // channel pair 0..31
    const int ty = threadIdx.y;          // local edge 0..7
    const int tid = ty * 32 + tx;
    const int e0 = blockIdx.x * 8;

    for (int idx = tid; idx < 8 * FD; idx += 256) {
        int le = idx >> 7;
        int k  = idx & (FD - 1);
        int e  = e0 + le;
        efs[le][k] = (e < E) ? ef[e * FD + k] : 0.f;
    }
    __syncthreads();

    const int e = e0 + ty;
    if (e >= E) return;

    const int c0 = 2 * tx;
    float2 a = *reinterpret_cast<const float2*>(&b1[c0]);
    float2 b = make_float2(0.f, 0.f);
#pragma unroll 8
    for (int k = 0; k < FD; ++k) {
        float s = efs[ty][k];
        float2 wa = *reinterpret_cast<const float2*>(&W1[k * H1D + c0]);
        float2 wb = *reinterpret_cast<const float2*>(&W1[(FD + k) * H1D + c0]);
        a.x = fmaf(s, wa.x, a.x);
        a.y = fmaf(s, wa.y, a.y);
        b.x = fmaf(s, wb.x, b.x);
        b.y = fmaf(s, wb.y, b.y);
    }
    *reinterpret_cast<float2*>(&g_A[e * H1D + c0]) = a;
    *reinterpret_cast<float2*>(&g_B[e * H1D + c0]) = b;
}

// ---------------------------------------------------------------------------
// Main kernel: one thread per pair.
// Gather A[i]+B[j] (fp32), accumulate LN stats on the fly, stage raw h1 as
// half2 in shared (private column per thread -> no sync needed), then
// LN+ReLU fused into the layer-2 matvec with float4 broadcast weight LDS,
// LN2+ReLU, layer-3 matvec, stage diag, cooperative coalesced streaming
// stores of the [16,16] diag-embed.
// ---------------------------------------------------------------------------
__global__ void __launch_bounds__(256, 3)
pairs_kernel(const int* __restrict__ pi, const int* __restrict__ pj,
             const float* __restrict__ g1, const float* __restrict__ be1,
             const float* __restrict__ W2, const float* __restrict__ b2,
             const float* __restrict__ g2, const float* __restrict__ be2,
             const float* __restrict__ W3, const float* __restrict__ b3,
             float* __restrict__ out, int P) {
    // h1 staging (32 KB) aliased with diag staging (16 KB): h1 is dead for all
    // threads before diag writes (guarded by an extra __syncthreads).
    __shared__ union {
        __half2 h1[H1D / 2][256];        // [kp][tid], 32 KB
        float   diag[256][DD];           // 16 KB
    } sh;
    __shared__ float W2s[H1D * H2D];     // 8 KB
    __shared__ float W3s[H2D * DD];      // 2 KB
    __shared__ float g1s[H1D], be1s[H1D];
    __shared__ float b2s[H2D], g2s[H2D], be2s[H2D], b3s[DD];

    const int tid = threadIdx.x;

    for (int idx = tid; idx < H1D * H2D; idx += 256) W2s[idx] = W2[idx];
    for (int idx = tid; idx < H2D * DD; idx += 256) W3s[idx] = W3[idx];
    if (tid < H1D) { g1s[tid] = g1[tid]; be1s[tid] = be1[tid]; }
    if (tid < H2D) { b2s[tid] = b2[tid]; g2s[tid] = g2[tid]; be2s[tid] = be2[tid]; }
    if (tid < DD)  { b3s[tid] = b3[tid]; }
    __syncthreads();

    const int p = blockIdx.x * 256 + tid;
    const bool active = (p < P);
    float pr[DD];
#pragma unroll
    for (int o = 0; o < DD; ++o) pr[o] = 0.f;

    if (active) {
        const int i = pi[p];
        const int j = pj[p];
        const float4* a4 = reinterpret_cast<const float4*>(g_A + (size_t)i * H1D);
        const float4* b4 = reinterpret_cast<const float4*>(g_B + (size_t)j * H1D);

        // Gather + stage raw h1 (half2) + accumulate LN stats in fp32.
        float sum = 0.f, sumsq = 0.f;
#pragma unroll
        for (int q = 0; q < H1D / 4; ++q) {
            float4 av = a4[q];
            float4 bv = b4[q];
            float s0 = av.x + bv.x;
            float s1 = av.y + bv.y;
            float s2 = av.z + bv.z;
            float s3 = av.w + bv.w;
            sh.h1[2 * q + 0][tid] = __floats2half2_rn(s0, s1);
            sh.h1[2 * q + 1][tid] = __floats2half2_rn(s2, s3);
            sum += (s0 + s1) + (s2 + s3);
            sumsq = fmaf(s0, s0, sumsq);
            sumsq = fmaf(s1, s1, sumsq);
            sumsq = fmaf(s2, s2, sumsq);
            sumsq = fmaf(s3, s3, sumsq);
        }
        const float mu = sum * (1.f / H1D);
        float var = sumsq * (1.f / H1D) - mu * mu;
        const float inv = rsqrtf(var + LN_EPS);

        // Layer 2: fused LN1+ReLU then [64] x [64,32], float4 weight LDS.
        float h2[H2D];
#pragma unroll
        for (int o = 0; o < H2D; ++o) h2[o] = b2s[o];
        const float4* W2s4 = reinterpret_cast<const float4*>(W2s);
#pragma unroll
        for (int kp = 0; kp < H1D / 2; ++kp) {
            float2 f = __half22float2(sh.h1[kp][tid]);
            float t0 = fmaxf(fmaf((f.x - mu) * inv, g1s[2 * kp + 0], be1s[2 * kp + 0]), 0.f);
            float t1 = fmaxf(fmaf((f.y - mu) * inv, g1s[2 * kp + 1], be1s[2 * kp + 1]), 0.f);
            const float4* w0 = W2s4 + (2 * kp + 0) * (H2D / 4);
            const float4* w1 = W2s4 + (2 * kp + 1) * (H2D / 4);
#pragma unroll
            for (int o4 = 0; o4 < H2D / 4; ++o4) {
                float4 wa = w0[o4];
                float4 wb = w1[o4];
                h2[4 * o4 + 0] = fmaf(t0, wa.x, h2[4 * o4 + 0]);
                h2[4 * o4 + 1] = fmaf(t0, wa.y, h2[4 * o4 + 1]);
                h2[4 * o4 + 2] = fmaf(t0, wa.z, h2[4 * o4 + 2]);
                h2[4 * o4 + 3] = fmaf(t0, wa.w, h2[4 * o4 + 3]);
                h2[4 * o4 + 0] = fmaf(t1, wb.x, h2[4 * o4 + 0]);
                h2[4 * o4 + 1] = fmaf(t1, wb.y, h2[4 * o4 + 1]);
                h2[4 * o4 + 2] = fmaf(t1, wb.z, h2[4 * o4 + 2]);
                h2[4 * o4 + 3] = fmaf(t1, wb.w, h2[4 * o4 + 3]);
            }
        }

        // LayerNorm over 32 + affine + ReLU
        float mu2 = 0.f;
#pragma unroll
        for (int k = 0; k < H2D; ++k) mu2 += h2[k];
        mu2 *= (1.f / H2D);
        float var2 = 0.f;
#pragma unroll
        for (int k = 0; k < H2D; ++k) { float d = h2[k] - mu2; var2 = fmaf(d, d, var2); }
        var2 *= (1.f / H2D);
        float inv2 = rsqrtf(var2 + LN_EPS);
#pragma unroll
        for (int k = 0; k < H2D; ++k) {
            float v = fmaf((h2[k] - mu2) * inv2, g2s[k], be2s[k]);
            h2[k] = fmaxf(v, 0.f);
        }

        // Layer 3: [32] x [32,16], float4 weight LDS.
#pragma unroll
        for (int o = 0; o < DD; ++o) pr[o] = b3s[o];
        const float4* W3s4 = reinterpret_cast<const float4*>(W3s);
#pragma unroll
        for (int k = 0; k < H2D; ++k) {
            float t = h2[k];
#pragma unroll
            for (int o4 = 0; o4 < DD / 4; ++o4) {
                float4 w = W3s4[k * (DD / 4) + o4];
                pr[4 * o4 + 0] = fmaf(t, w.x, pr[4 * o4 + 0]);
                pr[4 * o4 + 1] = fmaf(t, w.y, pr[4 * o4 + 1]);
                pr[4 * o4 + 2] = fmaf(t, w.z, pr[4 * o4 + 2]);
                pr[4 * o4 + 3] = fmaf(t, w.w, pr[4 * o4 + 3]);
            }
        }
    }

    // h1 region fully dead for ALL threads before diag overwrites it.
    __syncthreads();
#pragma unroll
    for (int o = 0; o < DD; ++o) sh.diag[tid][o] = pr[o];
    __syncthreads();

    // Cooperative coalesced store of the diag-embedded [256 pairs, 16, 16]
    // tile: 256 KB contiguous per block, streaming (bypass L2 persistence).
    const size_t blockBase4 = (size_t)blockIdx.x * (256 * 64);
    const size_t total4 = (size_t)P * 64;
    float4* o4p = reinterpret_cast<float4*>(out);
#pragma unroll 4
    for (int it = 0; it < 64; ++it) {
        const int local4 = it * 256 + tid;           // 0..16383
        const size_t f4 = blockBase4 + local4;
        if (f4 < total4) {
            const int lp = local4 >> 6;              // local pair (64 float4 each)
            const int w4 = local4 & 63;              // float4 index within pair
            const int row = w4 >> 2;                 // 4 float4 per 16-float row
            const int col0 = (w4 & 3) * 4;
            float4 v = make_float4(0.f, 0.f, 0.f, 0.f);
            const int d = row - col0;
            if (d >= 0 && d < 4) {
                reinterpret_cast<float*>(&v)[d] = sh.diag[lp][row];
            }
            __stcs(o4p + f4, v);
        }
    }
}

extern "C" void kernel_launch(void* const* d_in, const int* in_sizes, int n_in,
                              void* d_out, int out_size) {
    const float* ef  = (const float*)d_in[0];
    const int*   pi  = (const int*)d_in[1];
    const int*   pj  = (const int*)d_in[2];
    const float* W1  = (const float*)d_in[3];
    const float* b1  = (const float*)d_in[4];
    const float* g1  = (const float*)d_in[5];
    const float* be1 = (const float*)d_in[6];
    const float* W2  = (const float*)d_in[7];
    const float* b2  = (const float*)d_in[8];
    const float* g2  = (const float*)d_in[9];
    const float* be2 = (const float*)d_in[10];
    const float* W3  = (const float*)d_in[11];
    const float* b3  = (const float*)d_in[12];
    float* out = (float*)d_out;

    const int E = in_sizes[0] / FD;
    const int P = in_sizes[1];

    dim3 pb(32, 8);
    precompute_kernel<<<(E + 7) / 8, pb>>>(ef, W1, b1, E);

    const int blocks = (P + 255) / 256;
    pairs_kernel<<<blocks, 256>>>(pi, pj, g1, be1, W2, b2, g2, be2, W3, b3, out, P);
}

// round 5
// speedup vs baseline: 1.1546x; 1.0532x over previous
#include <cuda_runtime.h>
#include <cuda_fp16.h>

#define E_MAX 20000
#define FD 128
#define H1D 64
#define H2D 32
#define DD 16
#define LN_EPS 1e-5f

// Scratch: precomputed A = ef@W1[:128] + b1, B = ef@W1[128:]
__device__ float g_A[E_MAX * H1D];
__device__ float g_B[E_MAX * H1D];

// ---------------------------------------------------------------------------
// Precompute per-edge partial layer-1 outputs.
// blockDim = (32, 8): 32 edges per block; each thread owns 2 output channels
// for 4 edges, so each W1 float2 load is reused 4x from registers.
// ---------------------------------------------------------------------------
__global__ void precompute_kernel(const float* __restrict__ ef,
                                  const float* __restrict__ W1,
                                  const float* __restrict__ b1,
                                  int E) {
    __shared__ float efs[32][FD];        // 16 KB
    const int tx = threadIdx.x;          // channel pair 0..31
    const int ty = threadIdx.y;          // edge subgroup 0..7
    const int tid = ty * 32 + tx;
    const int e0 = blockIdx.x * 32;

    for (int idx = tid; idx < 32 * FD; idx += 256) {
        int le = idx >> 7;
        int k  = idx & (FD - 1);
        int e  = e0 + le;
        efs[le][k] = (e < E) ? ef[e * FD + k] : 0.f;
    }
    __syncthreads();

    const int c0 = 2 * tx;
    float2 bias = *reinterpret_cast<const float2*>(&b1[c0]);
    float2 a[4], b[4];
#pragma unroll
    for (int u = 0; u < 4; ++u) { a[u] = bias; b[u] = make_float2(0.f, 0.f); }

#pragma unroll 4
    for (int k = 0; k < FD; ++k) {
        float2 wa = *reinterpret_cast<const float2*>(&W1[k * H1D + c0]);
        float2 wb = *reinterpret_cast<const float2*>(&W1[(FD + k) * H1D + c0]);
#pragma unroll
        for (int u = 0; u < 4; ++u) {
            float s = efs[ty + 8 * u][k];
            a[u].x = fmaf(s, wa.x, a[u].x);
            a[u].y = fmaf(s, wa.y, a[u].y);
            b[u].x = fmaf(s, wb.x, b[u].x);
            b[u].y = fmaf(s, wb.y, b[u].y);
        }
    }
#pragma unroll
    for (int u = 0; u < 4; ++u) {
        const int e = e0 + ty + 8 * u;
        if (e < E) {
            *reinterpret_cast<float2*>(&g_A[e * H1D + c0]) = a[u];
            *reinterpret_cast<float2*>(&g_B[e * H1D + c0]) = b[u];
        }
    }
}

// ---------------------------------------------------------------------------
// Main kernel: warp-cooperative COALESCED gather of A[i]+B[j] rows (indices
// broadcast via shfl), staged as half2 in a pad-33 bank-conflict-free
// per-warp shared tile; then per-thread LN -> W2 matvec (float4 broadcast
// LDS) -> LN -> W3 matvec -> diag staging -> cooperative coalesced
// streaming stores of the [16,16] diag-embed.
// ---------------------------------------------------------------------------
__global__ void __launch_bounds__(256, 3)
pairs_kernel(const int* __restrict__ pi, const int* __restrict__ pj,
             const float* __restrict__ g1, const float* __restrict__ be1,
             const float* __restrict__ W2, const float* __restrict__ b2,
             const float* __restrict__ g2, const float* __restrict__ be2,
             const float* __restrict__ W3, const float* __restrict__ b3,
             float* __restrict__ out, int P) {
    // h1 tile (8 warps x 32 pairs x 33 half2 = 33792 B) aliased with diag
    // staging (16384 B): h1 dead for all threads before diag writes.
    __shared__ union {
        __half2 h1[8][32 * 33];
        float   diag[256][DD];
    } sh;
    __shared__ float W2s[H1D * H2D];     // 8 KB
    __shared__ float W3s[H2D * DD];      // 2 KB
    __shared__ float g1s[H1D], be1s[H1D];
    __shared__ float b2s[H2D], g2s[H2D], be2s[H2D], b3s[DD];

    const int tid  = threadIdx.x;
    const int warp = tid >> 5;
    const int lane = tid & 31;

    for (int idx = tid; idx < H1D * H2D; idx += 256) W2s[idx] = W2[idx];
    for (int idx = tid; idx < H2D * DD; idx += 256) W3s[idx] = W3[idx];
    if (tid < H1D) { g1s[tid] = g1[tid]; be1s[tid] = be1[tid]; }
    if (tid < H2D) { b2s[tid] = b2[tid]; g2s[tid] = g2[tid]; be2s[tid] = be2[tid]; }
    if (tid < DD)  { b3s[tid] = b3[tid]; }
    __syncthreads();

    const int pbase = blockIdx.x * 256 + warp * 32;
    const int myp   = pbase + lane;
    const bool active = (myp < P);

    // Each lane owns the indices of pair (pbase + lane); clamp inactive to 0.
    int il = 0, jl = 0;
    if (active) { il = pi[myp]; jl = pj[myp]; }

    __half2* h1w = sh.h1[warp];

    // Cooperative gather: one pair per iteration; lane -> channels (2l, 2l+1).
    // LDG fully coalesced (256 B/row = 2 lines); STS conflict-free (pad 33).
#pragma unroll 8
    for (int p = 0; p < 32; ++p) {
        const int ip = __shfl_sync(0xffffffffu, il, p);
        const int jp = __shfl_sync(0xffffffffu, jl, p);
        const float2 a = reinterpret_cast<const float2*>(g_A + (size_t)ip * H1D)[lane];
        const float2 b = reinterpret_cast<const float2*>(g_B + (size_t)jp * H1D)[lane];
        h1w[p * 33 + lane] = __floats2half2_rn(a.x + b.x, a.y + b.y);
    }
    __syncwarp();

    float pr[DD];
#pragma unroll
    for (int o = 0; o < DD; ++o) pr[o] = 0.f;

    if (active) {
        const __half2* myrow = h1w + lane * 33;   // bank = (lane+q)%32: conflict-free

        // Pass 1: LN stats.
        float sum = 0.f, sumsq = 0.f;
#pragma unroll
        for (int q = 0; q < H1D / 2; ++q) {
            float2 f = __half22float2(myrow[q]);
            sum += f.x + f.y;
            sumsq = fmaf(f.x, f.x, sumsq);
            sumsq = fmaf(f.y, f.y, sumsq);
        }
        const float mu = sum * (1.f / H1D);
        const float var = sumsq * (1.f / H1D) - mu * mu;
        const float inv = rsqrtf(var + LN_EPS);

        // Pass 2: fused LN1+ReLU into layer-2 matvec (float4 broadcast LDS).
        float h2[H2D];
#pragma unroll
        for (int o = 0; o < H2D; ++o) h2[o] = b2s[o];
        const float4* W2s4 = reinterpret_cast<const float4*>(W2s);
#pragma unroll
        for (int q = 0; q < H1D / 2; ++q) {
            float2 f = __half22float2(myrow[q]);
            float t0 = fmaxf(fmaf((f.x - mu) * inv, g1s[2 * q + 0], be1s[2 * q + 0]), 0.f);
            float t1 = fmaxf(fmaf((f.y - mu) * inv, g1s[2 * q + 1], be1s[2 * q + 1]), 0.f);
            const float4* w0 = W2s4 + (2 * q + 0) * (H2D / 4);
            const float4* w1 = W2s4 + (2 * q + 1) * (H2D / 4);
#pragma unroll
            for (int o4 = 0; o4 < H2D / 4; ++o4) {
                float4 wa = w0[o4];
                float4 wb = w1[o4];
                h2[4 * o4 + 0] = fmaf(t0, wa.x, h2[4 * o4 + 0]);
                h2[4 * o4 + 1] = fmaf(t0, wa.y, h2[4 * o4 + 1]);
                h2[4 * o4 + 2] = fmaf(t0, wa.z, h2[4 * o4 + 2]);
                h2[4 * o4 + 3] = fmaf(t0, wa.w, h2[4 * o4 + 3]);
                h2[4 * o4 + 0] = fmaf(t1, wb.x, h2[4 * o4 + 0]);
                h2[4 * o4 + 1] = fmaf(t1, wb.y, h2[4 * o4 + 1]);
                h2[4 * o4 + 2] = fmaf(t1, wb.z, h2[4 * o4 + 2]);
                h2[4 * o4 + 3] = fmaf(t1, wb.w, h2[4 * o4 + 3]);
            }
        }

        // LayerNorm over 32 + affine + ReLU.
        float mu2 = 0.f;
#pragma unroll
        for (int k = 0; k < H2D; ++k) mu2 += h2[k];
        mu2 *= (1.f / H2D);
        float var2 = 0.f;
#pragma unroll
        for (int k = 0; k < H2D; ++k) { float d = h2[k] - mu2; var2 = fmaf(d, d, var2); }
        var2 *= (1.f / H2D);
        const float inv2 = rsqrtf(var2 + LN_EPS);
#pragma unroll
        for (int k = 0; k < H2D; ++k) {
            float v = fmaf((h2[k] - mu2) * inv2, g2s[k], be2s[k]);
            h2[k] = fmaxf(v, 0.f);
        }

        // Layer 3: [32] x [32,16], float4 broadcast LDS.
#pragma unroll
        for (int o = 0; o < DD; ++o) pr[o] = b3s[o];
        const float4* W3s4 = reinterpret_cast<const float4*>(W3s);
#pragma unroll
        for (int k = 0; k < H2D; ++k) {
            float t = h2[k];
#pragma unroll
            for (int o4 = 0; o4 < DD / 4; ++o4) {
                float4 w = W3s4[k * (DD / 4) + o4];
                pr[4 * o4 + 0] = fmaf(t, w.x, pr[4 * o4 + 0]);
                pr[4 * o4 + 1] = fmaf(t, w.y, pr[4 * o4 + 1]);
                pr[4 * o4 + 2] = fmaf(t, w.z, pr[4 * o4 + 2]);
                pr[4 * o4 + 3] = fmaf(t, w.w, pr[4 * o4 + 3]);
            }
        }
    }

    // h1 tile fully dead for ALL threads before diag overwrites it.
    __syncthreads();
#pragma unroll
    for (int o = 0; o < DD; ++o) sh.diag[tid][o] = pr[o];
    __syncthreads();

    // Cooperative coalesced streaming stores of the [256, 16, 16] diag-embed.
    const size_t blockBase4 = (size_t)blockIdx.x * (256 * 64);
    const size_t total4 = (size_t)P * 64;
    float4* o4p = reinterpret_cast<float4*>(out);
#pragma unroll 4
    for (int it = 0; it < 64; ++it) {
        const int local4 = it * 256 + tid;           // 0..16383
        const size_t f4 = blockBase4 + local4;
        if (f4 < total4) {
            const int lp = local4 >> 6;              // local pair (64 float4 each)
            const int w4 = local4 & 63;              // float4 index within pair
            const int row = w4 >> 2;                 // 4 float4 per 16-float row
            const int col0 = (w4 & 3) * 4;
            float4 v = make_float4(0.f, 0.f, 0.f, 0.f);
            const int d = row - col0;
            if (d >= 0 && d < 4) {
                reinterpret_cast<float*>(&v)[d] = sh.diag[lp][row];
            }
            __stcs(o4p + f4, v);
        }
    }
}

extern "C" void kernel_launch(void* const* d_in, const int* in_sizes, int n_in,
                              void* d_out, int out_size) {
    const float* ef  = (const float*)d_in[0];
    const int*   pi  = (const int*)d_in[1];
    const int*   pj  = (const int*)d_in[2];
    const float* W1  = (const float*)d_in[3];
    const float* b1  = (const float*)d_in[4];
    const float* g1  = (const float*)d_in[5];
    const float* be1 = (const float*)d_in[6];
    const float* W2  = (const float*)d_in[7];
    const float* b2  = (const float*)d_in[8];
    const float* g2  = (const float*)d_in[9];
    const float* be2 = (const float*)d_in[10];
    const float* W3  = (const float*)d_in[11];
    const float* b3  = (const float*)d_in[12];
    float* out = (float*)d_out;

    const int E = in_sizes[0] / FD;
    const int P = in_sizes[1];

    dim3 pb(32, 8);
    precompute_kernel<<<(E + 31) / 32, pb>>>(ef, W1, b1, E);

    const int blocks = (P + 255) / 256;
    pairs_kernel<<<blocks, 256>>>(pi, pj, g1, be1, W2, b2, g2, be2, W3, b3, out, P);
}

// round 6
// speedup vs baseline: 1.2177x; 1.0546x over previous
#include <cuda_runtime.h>
#include <cuda_fp16.h>

#define E_MAX 20000
#define FD 128
#define H1D 64
#define H2D 32
#define DD 16
#define LN_EPS 1e-5f

// Scratch: precomputed A = ef@W1[:128] + b1, B = ef@W1[128:]
__device__ float g_A[E_MAX * H1D];
__device__ float g_B[E_MAX * H1D];

// ---------------------------------------------------------------------------
// Precompute per-edge partial layer-1 outputs.
// blockDim = (16, 16): 64 edges/block; each thread owns 4 output channels
// (float4 W1 loads) for 4 edges -> each W1 load feeds 32 FFMA.
// ---------------------------------------------------------------------------
__global__ void precompute_kernel(const float* __restrict__ ef,
                                  const float* __restrict__ W1,
                                  const float* __restrict__ b1,
                                  int E) {
    __shared__ float efs[64][FD + 1];    // pad 129: column reads conflict-free
    const int tx = threadIdx.x;          // channel quad 0..15
    const int ty = threadIdx.y;          // edge subgroup 0..15
    const int tid = ty * 16 + tx;
    const int e0 = blockIdx.x * 64;

    for (int idx = tid; idx < 64 * FD; idx += 256) {
        int le = idx >> 7;
        int k  = idx & (FD - 1);
        int e  = e0 + le;
        efs[le][k] = (e < E) ? ef[e * FD + k] : 0.f;
    }
    __syncthreads();

    const int c0 = 4 * tx;
    const float4 bias = *reinterpret_cast<const float4*>(&b1[c0]);
    float4 a[4], b[4];
#pragma unroll
    for (int u = 0; u < 4; ++u) {
        a[u] = bias;
        b[u] = make_float4(0.f, 0.f, 0.f, 0.f);
    }

#pragma unroll 4
    for (int k = 0; k < FD; ++k) {
        const float4 wa = *reinterpret_cast<const float4*>(&W1[k * H1D + c0]);
        const float4 wb = *reinterpret_cast<const float4*>(&W1[(FD + k) * H1D + c0]);
#pragma unroll
        for (int u = 0; u < 4; ++u) {
            const float s = efs[ty + 16 * u][k];
            a[u].x = fmaf(s, wa.x, a[u].x);
            a[u].y = fmaf(s, wa.y, a[u].y);
            a[u].z = fmaf(s, wa.z, a[u].z);
            a[u].w = fmaf(s, wa.w, a[u].w);
            b[u].x = fmaf(s, wb.x, b[u].x);
            b[u].y = fmaf(s, wb.y, b[u].y);
            b[u].z = fmaf(s, wb.z, b[u].z);
            b[u].w = fmaf(s, wb.w, b[u].w);
        }
    }
#pragma unroll
    for (int u = 0; u < 4; ++u) {
        const int e = e0 + ty + 16 * u;
        if (e < E) {
            *reinterpret_cast<float4*>(&g_A[e * H1D + c0]) = a[u];
            *reinterpret_cast<float4*>(&g_B[e * H1D + c0]) = b[u];
        }
    }
}

// ---------------------------------------------------------------------------
// Main kernel: 128 threads, 2 pairs per thread (64 pairs/warp, 256/block).
// Warp-cooperative coalesced gather -> pad-33 half2 h1 tile -> per-thread
// dual-pair MLP sharing every W2/W3 float4 LDS between both pairs ->
// pad-17 conflict-free diag staging -> coalesced streaming stores.
// ---------------------------------------------------------------------------
__global__ void __launch_bounds__(128, 4)
pairs_kernel(const int* __restrict__ pi, const int* __restrict__ pj,
             const float* __restrict__ g1, const float* __restrict__ be1,
             const float* __restrict__ W2, const float* __restrict__ b2,
             const float* __restrict__ g2, const float* __restrict__ be2,
             const float* __restrict__ W3, const float* __restrict__ b3,
             float* __restrict__ out, int P) {
    // h1 tile (4 warps x 64 pairs x 33 half2 = 33792 B) aliased with pad-17
    // diag staging (256*17*4 = 17408 B): h1 dead before diag writes.
    __shared__ union {
        __half2 h1[4][64 * 33];
        float   diag[256 * 17];
    } sh;
    __shared__ float W2s[H1D * H2D];     // 8 KB
    __shared__ float W3s[H2D * DD];      // 2 KB
    __shared__ float g1s[H1D], be1s[H1D];
    __shared__ float b2s[H2D], g2s[H2D], be2s[H2D], b3s[DD];

    const int tid  = threadIdx.x;
    const int warp = tid >> 5;
    const int lane = tid & 31;

    for (int idx = tid; idx < H1D * H2D; idx += 128) W2s[idx] = W2[idx];
    for (int idx = tid; idx < H2D * DD; idx += 128) W3s[idx] = W3[idx];
    if (tid < H1D) { g1s[tid] = g1[tid]; be1s[tid] = be1[tid]; }
    if (tid < H2D) { b2s[tid] = b2[tid]; g2s[tid] = g2[tid]; be2s[tid] = be2[tid]; }
    if (tid < DD)  { b3s[tid] = b3[tid]; }
    __syncthreads();

    const int pbase = blockIdx.x * 256 + warp * 64;
    const int pA = pbase + lane;
    const int pB = pbase + 32 + lane;

    int ilA = 0, jlA = 0, ilB = 0, jlB = 0;
    if (pA < P) { ilA = pi[pA]; jlA = pj[pA]; }
    if (pB < P) { ilB = pi[pB]; jlB = pj[pB]; }

    __half2* h1w = sh.h1[warp];

    // Cooperative gather: 64 pairs; lane -> channels (2l, 2l+1).
    // LDG coalesced (256 B/row); STS conflict-free (pad 33).
#pragma unroll 8
    for (int p = 0; p < 64; ++p) {
        const int srcI = (p < 32) ? ilA : ilB;
        const int srcJ = (p < 32) ? jlA : jlB;
        const int ip = __shfl_sync(0xffffffffu, srcI, p & 31);
        const int jp = __shfl_sync(0xffffffffu, srcJ, p & 31);
        const float2 a = reinterpret_cast<const float2*>(g_A + (size_t)ip * H1D)[lane];
        const float2 b = reinterpret_cast<const float2*>(g_B + (size_t)jp * H1D)[lane];
        h1w[p * 33 + lane] = __floats2half2_rn(a.x + b.x, a.y + b.y);
    }
    __syncwarp();

    // Column readback: bank (lane+q)%32 and (lane+q)%32 shifted by 1056%32=0:
    // both conflict-free.
    const __half2* rA = h1w + lane * 33;
    const __half2* rB = h1w + (lane + 32) * 33;

    // Pass 1: LN stats, both pairs.
    float sumA = 0.f, sqA = 0.f, sumB = 0.f, sqB = 0.f;
#pragma unroll
    for (int q = 0; q < H1D / 2; ++q) {
        const float2 fA = __half22float2(rA[q]);
        const float2 fB = __half22float2(rB[q]);
        sumA += fA.x + fA.y;
        sqA = fmaf(fA.x, fA.x, sqA);
        sqA = fmaf(fA.y, fA.y, sqA);
        sumB += fB.x + fB.y;
        sqB = fmaf(fB.x, fB.x, sqB);
        sqB = fmaf(fB.y, fB.y, sqB);
    }
    const float muA = sumA * (1.f / H1D);
    const float invA = rsqrtf(sqA * (1.f / H1D) - muA * muA + LN_EPS);
    const float muB = sumB * (1.f / H1D);
    const float invB = rsqrtf(sqB * (1.f / H1D) - muB * muB + LN_EPS);

    // Pass 2: fused LN1+ReLU into layer-2 matvec; each weight float4 LDS
    // feeds both pairs.
    float h2A[H2D], h2B[H2D];
#pragma unroll
    for (int o = 0; o < H2D; ++o) { h2A[o] = b2s[o]; h2B[o] = b2s[o]; }
    const float4* W2s4 = reinterpret_cast<const float4*>(W2s);
#pragma unroll
    for (int q = 0; q < H1D / 2; ++q) {
        const float2 fA = __half22float2(rA[q]);
        const float2 fB = __half22float2(rB[q]);
        const float ga0 = g1s[2 * q + 0], ga1 = g1s[2 * q + 1];
        const float ba0 = be1s[2 * q + 0], ba1 = be1s[2 * q + 1];
        const float tA0 = fmaxf(fmaf((fA.x - muA) * invA, ga0, ba0), 0.f);
        const float tA1 = fmaxf(fmaf((fA.y - muA) * invA, ga1, ba1), 0.f);
        const float tB0 = fmaxf(fmaf((fB.x - muB) * invB, ga0, ba0), 0.f);
        const float tB1 = fmaxf(fmaf((fB.y - muB) * invB, ga1, ba1), 0.f);
        const float4* w0 = W2s4 + (2 * q + 0) * (H2D / 4);
        const float4* w1 = W2s4 + (2 * q + 1) * (H2D / 4);
#pragma unroll
        for (int o4 = 0; o4 < H2D / 4; ++o4) {
            const float4 wa = w0[o4];
            const float4 wb = w1[o4];
            h2A[4 * o4 + 0] = fmaf(tA0, wa.x, h2A[4 * o4 + 0]);
            h2A[4 * o4 + 1] = fmaf(tA0, wa.y, h2A[4 * o4 + 1]);
            h2A[4 * o4 + 2] = fmaf(tA0, wa.z, h2A[4 * o4 + 2]);
            h2A[4 * o4 + 3] = fmaf(tA0, wa.w, h2A[4 * o4 + 3]);
            h2A[4 * o4 + 0] = fmaf(tA1, wb.x, h2A[4 * o4 + 0]);
            h2A[4 * o4 + 1] = fmaf(tA1, wb.y, h2A[4 * o4 + 1]);
            h2A[4 * o4 + 2] = fmaf(tA1, wb.z, h2A[4 * o4 + 2]);
            h2A[4 * o4 + 3] = fmaf(tA1, wb.w, h2A[4 * o4 + 3]);
            h2B[4 * o4 + 0] = fmaf(tB0, wa.x, h2B[4 * o4 + 0]);
            h2B[4 * o4 + 1] = fmaf(tB0, wa.y, h2B[4 * o4 + 1]);
            h2B[4 * o4 + 2] = fmaf(tB0, wa.z, h2B[4 * o4 + 2]);
            h2B[4 * o4 + 3] = fmaf(tB0, wa.w, h2B[4 * o4 + 3]);
            h2B[4 * o4 + 0] = fmaf(tB1, wb.x, h2B[4 * o4 + 0]);
            h2B[4 * o4 + 1] = fmaf(tB1, wb.y, h2B[4 * o4 + 1]);
            h2B[4 * o4 + 2] = fmaf(tB1, wb.z, h2B[4 * o4 + 2]);
            h2B[4 * o4 + 3] = fmaf(tB1, wb.w, h2B[4 * o4 + 3]);
        }
    }

    // LayerNorm over 32 + affine + ReLU, both pairs.
    float mu2A = 0.f, mu2B = 0.f;
#pragma unroll
    for (int k = 0; k < H2D; ++k) { mu2A += h2A[k]; mu2B += h2B[k]; }
    mu2A *= (1.f / H2D);
    mu2B *= (1.f / H2D);
    float v2A = 0.f, v2B = 0.f;
#pragma unroll
    for (int k = 0; k < H2D; ++k) {
        const float dA = h2A[k] - mu2A; v2A = fmaf(dA, dA, v2A);
        const float dB = h2B[k] - mu2B; v2B = fmaf(dB, dB, v2B);
    }
    const float inv2A = rsqrtf(v2A * (1.f / H2D) + LN_EPS);
    const float inv2B = rsqrtf(v2B * (1.f / H2D) + LN_EPS);
#pragma unroll
    for (int k = 0; k < H2D; ++k) {
        h2A[k] = fmaxf(fmaf((h2A[k] - mu2A) * inv2A, g2s[k], be2s[k]), 0.f);
        h2B[k] = fmaxf(fmaf((h2B[k] - mu2B) * inv2B, g2s[k], be2s[k]), 0.f);
    }

    // Layer 3: shared float4 weight LDS feeding both pairs.
    float prA[DD], prB[DD];
#pragma unroll
    for (int o = 0; o < DD; ++o) { prA[o] = b3s[o]; prB[o] = b3s[o]; }
    const float4* W3s4 = reinterpret_cast<const float4*>(W3s);
#pragma unroll
    for (int k = 0; k < H2D; ++k) {
        const float tA = h2A[k];
        const float tB = h2B[k];
#pragma unroll
        for (int o4 = 0; o4 < DD / 4; ++o4) {
            const float4 w = W3s4[k * (DD / 4) + o4];
            prA[4 * o4 + 0] = fmaf(tA, w.x, prA[4 * o4 + 0]);
            prA[4 * o4 + 1] = fmaf(tA, w.y, prA[4 * o4 + 1]);
            prA[4 * o4 + 2] = fmaf(tA, w.z, prA[4 * o4 + 2]);
            prA[4 * o4 + 3] = fmaf(tA, w.w, prA[4 * o4 + 3]);
            prB[4 * o4 + 0] = fmaf(tB, w.x, prB[4 * o4 + 0]);
            prB[4 * o4 + 1] = fmaf(tB, w.y, prB[4 * o4 + 1]);
            prB[4 * o4 + 2] = fmaf(tB, w.z, prB[4 * o4 + 2]);
            prB[4 * o4 + 3] = fmaf(tB, w.w, prB[4 * o4 + 3]);
        }
    }

    // h1 tile fully dead for ALL threads before diag overwrites it.
    __syncthreads();
    const int rowA = warp * 64 + lane;          // local pair indices
#pragma unroll
    for (int o = 0; o < DD; ++o) sh.diag[rowA * 17 + o] = prA[o];
#pragma unroll
    for (int o = 0; o < DD; ++o) sh.diag[(rowA + 32) * 17 + o] = prB[o];
    __syncthreads();

    // Cooperative coalesced streaming stores of the [256, 16, 16] diag-embed.
    const size_t blockBase4 = (size_t)blockIdx.x * (256 * 64);
    const size_t total4 = (size_t)P * 64;
    float4* o4p = reinterpret_cast<float4*>(out);
#pragma unroll 4
    for (int it = 0; it < 128; ++it) {
        const int local4 = it * 128 + tid;           // 0..16383
        const size_t f4 = blockBase4 + local4;
        if (f4 < total4) {
            const int lp = local4 >> 6;              // local pair (64 float4 each)
            const int w4 = local4 & 63;              // float4 index within pair
            const int row = w4 >> 2;                 // 4 float4 per 16-float row
            const int col0 = (w4 & 3) * 4;
            float4 v = make_float4(0.f, 0.f, 0.f, 0.f);
            const int d = row - col0;
            if (d >= 0 && d < 4) {
                reinterpret_cast<float*>(&v)[d] = sh.diag[lp * 17 + row];
            }
            __stcs(o4p + f4, v);
        }
    }
}

extern "C" void kernel_launch(void* const* d_in, const int* in_sizes, int n_in,
                              void* d_out, int out_size) {
    const float* ef  = (const float*)d_in[0];
    const int*   pi  = (const int*)d_in[1];
    const int*   pj  = (const int*)d_in[2];
    const float* W1  = (const float*)d_in[3];
    const float* b1  = (const float*)d_in[4];
    const float* g1  = (const float*)d_in[5];
    const float* be1 = (const float*)d_in[6];
    const float* W2  = (const float*)d_in[7];
    const float* b2  = (const float*)d_in[8];
    const float* g2  = (const float*)d_in[9];
    const float* be2 = (const float*)d_in[10];
    const float* W3  = (const float*)d_in[11];
    const float* b3  = (const float*)d_in[12];
    float* out = (float*)d_out;

    const int E = in_sizes[0] / FD;
    const int P = in_sizes[1];

    dim3 pb(16, 16);
    precompute_kernel<<<(E + 63) / 64, pb>>>(ef, W1, b1, E);

    const int blocks = (P + 255) / 256;
    pairs_kernel<<<blocks, 128>>>(pi, pj, g1, be1, W2, b2, g2, be2, W3, b3, out, P);
}

// round 7
// speedup vs baseline: 1.6820x; 1.3813x over previous
#include <cuda_runtime.h>
#include <cuda_fp16.h>
#include <cstdint>

#define E_MAX 20000
#define FD 128
#define H1D 64
#define H2D 32
#define DD 16
#define LN_EPS 1e-5f
#define ROWP 72   // halves per h1 row (144 B): ldmatrix rows shift 4 banks/row

// Scratch: precomputed A = ef@W1[:128] + b1, B = ef@W1[128:]
__device__ float g_A[E_MAX * H1D];
__device__ float g_B[E_MAX * H1D];

// ---------------------------------------------------------------------------
// Precompute per-edge partial layer-1 outputs (unchanged from R6).
// ---------------------------------------------------------------------------
__global__ void precompute_kernel(const float* __restrict__ ef,
                                  const float* __restrict__ W1,
                                  const float* __restrict__ b1,
                                  int E) {
    __shared__ float efs[64][FD + 1];
    const int tx = threadIdx.x;          // channel quad 0..15
    const int ty = threadIdx.y;          // edge subgroup 0..15
    const int tid = ty * 16 + tx;
    const int e0 = blockIdx.x * 64;

    for (int idx = tid; idx < 64 * FD; idx += 256) {
        int le = idx >> 7;
        int k  = idx & (FD - 1);
        int e  = e0 + le;
        efs[le][k] = (e < E) ? ef[e * FD + k] : 0.f;
    }
    __syncthreads();

    const int c0 = 4 * tx;
    const float4 bias = *reinterpret_cast<const float4*>(&b1[c0]);
    float4 a[4], b[4];
#pragma unroll
    for (int u = 0; u < 4; ++u) { a[u] = bias; b[u] = make_float4(0.f, 0.f, 0.f, 0.f); }

#pragma unroll 4
    for (int k = 0; k < FD; ++k) {
        const float4 wa = *reinterpret_cast<const float4*>(&W1[k * H1D + c0]);
        const float4 wb = *reinterpret_cast<const float4*>(&W1[(FD + k) * H1D + c0]);
#pragma unroll
        for (int u = 0; u < 4; ++u) {
            const float s = efs[ty + 16 * u][k];
            a[u].x = fmaf(s, wa.x, a[u].x); a[u].y = fmaf(s, wa.y, a[u].y);
            a[u].z = fmaf(s, wa.z, a[u].z); a[u].w = fmaf(s, wa.w, a[u].w);
            b[u].x = fmaf(s, wb.x, b[u].x); b[u].y = fmaf(s, wb.y, b[u].y);
            b[u].z = fmaf(s, wb.z, b[u].z); b[u].w = fmaf(s, wb.w, b[u].w);
        }
    }
#pragma unroll
    for (int u = 0; u < 4; ++u) {
        const int e = e0 + ty + 16 * u;
        if (e < E) {
            *reinterpret_cast<float4*>(&g_A[e * H1D + c0]) = a[u];
            *reinterpret_cast<float4*>(&g_B[e * H1D + c0]) = b[u];
        }
    }
}

// ---------------------------------------------------------------------------
// Helpers
// ---------------------------------------------------------------------------
__device__ __forceinline__ uint32_t smem_u32(const void* p) {
    return (uint32_t)__cvta_generic_to_shared(p);
}
__device__ __forceinline__ void ldmatrix_x4(uint32_t& a0, uint32_t& a1,
                                            uint32_t& a2, uint32_t& a3,
                                            uint32_t addr) {
    asm volatile("ldmatrix.sync.aligned.m8n8.x4.shared.b16 {%0,%1,%2,%3}, [%4];"
                 : "=r"(a0), "=r"(a1), "=r"(a2), "=r"(a3) : "r"(addr));
}
__device__ __forceinline__ void mma16816(float* c,
                                         uint32_t a0, uint32_t a1, uint32_t a2, uint32_t a3,
                                         uint32_t b0, uint32_t b1) {
    asm volatile("mma.sync.aligned.m16n8k16.row.col.f32.f16.f16.f32 "
                 "{%0,%1,%2,%3}, {%4,%5,%6,%7}, {%8,%9}, {%0,%1,%2,%3};"
                 : "+f"(c[0]), "+f"(c[1]), "+f"(c[2]), "+f"(c[3])
                 : "r"(a0), "r"(a1), "r"(a2), "r"(a3), "r"(b0), "r"(b1));
}
__device__ __forceinline__ uint32_t packh2(float lo, float hi) {
    __half2 h = __floats2half2_rn(lo, hi);
    return *reinterpret_cast<uint32_t*>(&h);
}

// ---------------------------------------------------------------------------
// Main kernel: 128 threads / 4 warps / 128 pairs per block.
// Per warp (32 pairs): coalesced gather + fused LN1 (fp32 stats via 16-lane
// butterfly) -> fp16 h1 tile (pad-72) -> ldmatrix + 32x HMMA layer2 ->
// register LN2 (quad shfl) -> 8x HMMA layer3 -> pad-17 diag staging ->
// block-cooperative coalesced streaming stores.
// ---------------------------------------------------------------------------
__global__ void __launch_bounds__(128)
pairs_kernel(const int* __restrict__ pi, const int* __restrict__ pj,
             const float* __restrict__ g1, const float* __restrict__ be1,
             const float* __restrict__ W2, const float* __restrict__ b2,
             const float* __restrict__ g2, const float* __restrict__ be2,
             const float* __restrict__ W3, const float* __restrict__ b3,
             float* __restrict__ out, int P) {
    __shared__ union {
        struct { float W2t[H1D * H2D]; float W3t[H2D * DD]; } st;  // 10240 B
        __half h1[4][32 * ROWP];                                    // 18432 B
        float  diag[128 * 17];                                      //  8704 B
    } sh;
    __shared__ float g1s[H1D], be1s[H1D], b2s[H2D], g2s[H2D], be2s[H2D], b3s[DD];

    const int tid  = threadIdx.x;
    const int warp = tid >> 5;
    const int lane = tid & 31;
    const int qr   = lane & 3;    // thread-in-quad (mma fragment col pair)
    const int qc   = lane >> 2;   // quad id       (mma fragment row)

    // Stage weights (coalesced) + biases.
    for (int i = tid; i < H1D * H2D; i += 128) sh.st.W2t[i] = W2[i];
    for (int i = tid; i < H2D * DD; i += 128) sh.st.W3t[i] = W3[i];
    if (tid < H1D) { g1s[tid] = g1[tid]; be1s[tid] = be1[tid]; }
    if (tid < H2D) { b2s[tid] = b2[tid]; g2s[tid] = g2[tid]; be2s[tid] = be2[tid]; }
    if (tid < DD)  { b3s[tid] = b3[tid]; }
    __syncthreads();

    // Build per-thread fp16 B-fragments for W2 (4 Ksteps x 4 Ntiles) and
    // W3 (2 Ksteps x 2 Ntiles). m16n8k16 B layout: k = 2*qr + {0,1} (+8 for
    // reg1), n = qc, within each (16k x 8n) tile.
    uint32_t w2f[4][4][2];
#pragma unroll
    for (int s = 0; s < 4; ++s)
#pragma unroll
        for (int t = 0; t < 4; ++t) {
            const int k0 = 16 * s + 2 * qr;
            const int n  = 8 * t + qc;
            w2f[s][t][0] = packh2(sh.st.W2t[(k0 + 0) * H2D + n], sh.st.W2t[(k0 + 1) * H2D + n]);
            w2f[s][t][1] = packh2(sh.st.W2t[(k0 + 8) * H2D + n], sh.st.W2t[(k0 + 9) * H2D + n]);
        }
    uint32_t w3f[2][2][2];
#pragma unroll
    for (int s = 0; s < 2; ++s)
#pragma unroll
        for (int u = 0; u < 2; ++u) {
            const int k0 = 16 * s + 2 * qr;
            const int n  = 8 * u + qc;
            w3f[s][u][0] = packh2(sh.st.W3t[(k0 + 0) * DD + n], sh.st.W3t[(k0 + 1) * DD + n]);
            w3f[s][u][1] = packh2(sh.st.W3t[(k0 + 8) * DD + n], sh.st.W3t[(k0 + 9) * DD + n]);
        }
    __syncthreads();   // weight staging dead; h1 region free

    // Pair indices (lane l owns pair pbase+l).
    const int pbase = blockIdx.x * 128 + warp * 32;
    const int myp = pbase + lane;
    int il = 0, jl = 0;
    if (myp < P) { il = pi[myp]; jl = pj[myp]; }

    // Gather + LN1: 2 pairs / iteration; 16-lane groups; lane covers 4 chans.
    const int lc = lane & 15, lg = lane >> 4;
    const float4 g1v  = *reinterpret_cast<const float4*>(&g1s[4 * lc]);
    const float4 be1v = *reinterpret_cast<const float4*>(&be1s[4 * lc]);
    __half* h1w = sh.h1[warp];

#pragma unroll 4
    for (int p = 0; p < 16; ++p) {
        const int src = 2 * p + lg;
        const int ip = __shfl_sync(0xffffffffu, il, src);
        const int jp = __shfl_sync(0xffffffffu, jl, src);
        const float4 a = reinterpret_cast<const float4*>(g_A + (size_t)ip * H1D)[lc];
        const float4 b = reinterpret_cast<const float4*>(g_B + (size_t)jp * H1D)[lc];
        const float s0 = a.x + b.x, s1 = a.y + b.y, s2 = a.z + b.z, s3 = a.w + b.w;
        float sum = (s0 + s1) + (s2 + s3);
        float sq  = fmaf(s0, s0, fmaf(s1, s1, fmaf(s2, s2, s3 * s3)));
#pragma unroll
        for (int mk = 1; mk <= 8; mk <<= 1) {
            sum += __shfl_xor_sync(0xffffffffu, sum, mk);
            sq  += __shfl_xor_sync(0xffffffffu, sq,  mk);
        }
        const float mu  = sum * (1.f / H1D);
        const float inv = rsqrtf(sq * (1.f / H1D) - mu * mu + LN_EPS);
        const float t0 = fmaxf(fmaf((s0 - mu) * inv, g1v.x, be1v.x), 0.f);
        const float t1 = fmaxf(fmaf((s1 - mu) * inv, g1v.y, be1v.y), 0.f);
        const float t2 = fmaxf(fmaf((s2 - mu) * inv, g1v.z, be1v.z), 0.f);
        const float t3 = fmaxf(fmaf((s3 - mu) * inv, g1v.w, be1v.w), 0.f);
        // STS.64: row (2p+lg), halves 4*lc..4*lc+3 (8B aligned, conflict-free)
        *reinterpret_cast<uint2*>(h1w + src * ROWP + 4 * lc) =
            make_uint2(packh2(t0, t1), packh2(t2, t3));
    }
    __syncwarp();

    // Layer 2: 2 Mtiles x 4 Ksteps x 4 Ntiles of m16n8k16.
    const int lrow  = (lane & 7) | (((lane >> 3) & 1) << 3);
    const int lcol8 = ((lane >> 4) & 1) * 8;
    const uint32_t h1base = smem_u32(h1w) + (uint32_t)(lrow * ROWP + lcol8) * 2u;

    float acc[2][4][4];
#pragma unroll
    for (int m = 0; m < 2; ++m)
#pragma unroll
        for (int t = 0; t < 4; ++t)
#pragma unroll
            for (int e = 0; e < 4; ++e) acc[m][t][e] = 0.f;

#pragma unroll
    for (int m = 0; m < 2; ++m)
#pragma unroll
        for (int s = 0; s < 4; ++s) {
            uint32_t a0, a1, a2, a3;
            ldmatrix_x4(a0, a1, a2, a3,
                        h1base + (uint32_t)((16 * m * ROWP + 16 * s) * 2));
#pragma unroll
            for (int t = 0; t < 4; ++t)
                mma16816(acc[m][t], a0, a1, a2, a3, w2f[s][t][0], w2f[s][t][1]);
        }
    __syncthreads();   // all h1 reads done block-wide; diag may alias now

    // Epilogue per Mtile: +b2, LN2 (quad reduce), ReLU, fp16 pack (C->A
    // identity), layer-3 mma, diag staging.
#pragma unroll
    for (int m = 0; m < 2; ++m) {
        float v[4][4];
        float sum0 = 0.f, sq0 = 0.f, sum1 = 0.f, sq1 = 0.f;
#pragma unroll
        for (int t = 0; t < 4; ++t) {
            const int n0 = 8 * t + 2 * qr;
            const float bb0 = b2s[n0], bb1 = b2s[n0 + 1];
            v[t][0] = acc[m][t][0] + bb0;
            v[t][1] = acc[m][t][1] + bb1;
            v[t][2] = acc[m][t][2] + bb0;
            v[t][3] = acc[m][t][3] + bb1;
            sum0 += v[t][0] + v[t][1];
            sq0 = fmaf(v[t][0], v[t][0], fmaf(v[t][1], v[t][1], sq0));
            sum1 += v[t][2] + v[t][3];
            sq1 = fmaf(v[t][2], v[t][2], fmaf(v[t][3], v[t][3], sq1));
        }
#pragma unroll
        for (int mk = 1; mk <= 2; mk <<= 1) {
            sum0 += __shfl_xor_sync(0xffffffffu, sum0, mk);
            sq0  += __shfl_xor_sync(0xffffffffu, sq0,  mk);
            sum1 += __shfl_xor_sync(0xffffffffu, sum1, mk);
            sq1  += __shfl_xor_sync(0xffffffffu, sq1,  mk);
        }
        const float mu0  = sum0 * (1.f / H2D);
        const float inv0 = rsqrtf(sq0 * (1.f / H2D) - mu0 * mu0 + LN_EPS);
        const float mu1  = sum1 * (1.f / H2D);
        const float inv1 = rsqrtf(sq1 * (1.f / H2D) - mu1 * mu1 + LN_EPS);

        uint32_t a3f[4][2];
#pragma unroll
        for (int t = 0; t < 4; ++t) {
            const int n0 = 8 * t + 2 * qr;
            const float gg0 = g2s[n0], gg1 = g2s[n0 + 1];
            const float eb0 = be2s[n0], eb1 = be2s[n0 + 1];
            const float h0 = fmaxf(fmaf((v[t][0] - mu0) * inv0, gg0, eb0), 0.f);
            const float h1v = fmaxf(fmaf((v[t][1] - mu0) * inv0, gg1, eb1), 0.f);
            const float h2v = fmaxf(fmaf((v[t][2] - mu1) * inv1, gg0, eb0), 0.f);
            const float h3v = fmaxf(fmaf((v[t][3] - mu1) * inv1, gg1, eb1), 0.f);
            a3f[t][0] = packh2(h0, h1v);
            a3f[t][1] = packh2(h2v, h3v);
        }

        float d[2][4];
#pragma unroll
        for (int u = 0; u < 2; ++u) {
            const int n0 = 8 * u + 2 * qr;
            d[u][0] = b3s[n0]; d[u][1] = b3s[n0 + 1];
            d[u][2] = b3s[n0]; d[u][3] = b3s[n0 + 1];
        }
#pragma unroll
        for (int s = 0; s < 2; ++s) {
            const uint32_t A0 = a3f[2 * s][0], A1 = a3f[2 * s][1];
            const uint32_t A2 = a3f[2 * s + 1][0], A3v = a3f[2 * s + 1][1];
#pragma unroll
            for (int u = 0; u < 2; ++u)
                mma16816(d[u], A0, A1, A2, A3v, w3f[s][u][0], w3f[s][u][1]);
        }

        const int r0 = warp * 32 + 16 * m + qc;
#pragma unroll
        for (int u = 0; u < 2; ++u) {
            const int n0 = 8 * u + 2 * qr;
            sh.diag[r0 * 17 + n0]           = d[u][0];
            sh.diag[r0 * 17 + n0 + 1]       = d[u][1];
            sh.diag[(r0 + 8) * 17 + n0]     = d[u][2];
            sh.diag[(r0 + 8) * 17 + n0 + 1] = d[u][3];
        }
    }
    __syncthreads();

    // Cooperative coalesced streaming stores of the [128, 16, 16] diag-embed.
    const size_t blockBase4 = (size_t)blockIdx.x * (128 * 64);
    const size_t total4 = (size_t)P * 64;
    float4* o4p = reinterpret_cast<float4*>(out);
#pragma unroll 4
    for (int it = 0; it < 64; ++it) {
        const int local4 = it * 128 + tid;           // 0..8191
        const size_t f4 = blockBase4 + local4;
        if (f4 < total4) {
            const int lp = local4 >> 6;              // local pair
            const int w4 = local4 & 63;
            const int row = w4 >> 2;
            const int col0 = (w4 & 3) * 4;
            float4 val = make_float4(0.f, 0.f, 0.f, 0.f);
            const int dd = row - col0;
            if (dd >= 0 && dd < 4) {
                reinterpret_cast<float*>(&val)[dd] = sh.diag[lp * 17 + row];
            }
            __stcs(o4p + f4, val);
        }
    }
}

extern "C" void kernel_launch(void* const* d_in, const int* in_sizes, int n_in,
                              void* d_out, int out_size) {
    const float* ef  = (const float*)d_in[0];
    const int*   pi  = (const int*)d_in[1];
    const int*   pj  = (const int*)d_in[2];
    const float* W1  = (const float*)d_in[3];
    const float* b1  = (const float*)d_in[4];
    const float* g1  = (const float*)d_in[5];
    const float* be1 = (const float*)d_in[6];
    const float* W2  = (const float*)d_in[7];
    const float* b2  = (const float*)d_in[8];
    const float* g2  = (const float*)d_in[9];
    const float* be2 = (const float*)d_in[10];
    const float* W3  = (const float*)d_in[11];
    const float* b3  = (const float*)d_in[12];
    float* out = (float*)d_out;

    const int E = in_sizes[0] / FD;
    const int P = in_sizes[1];

    dim3 pb(16, 16);
    precompute_kernel<<<(E + 63) / 64, pb>>>(ef, W1, b1, E);

    const int blocks = (P + 127) / 128;
    pairs_kernel<<<blocks, 128>>>(pi, pj, g1, be1, W2, b2, g2, be2, W3, b3, out, P);
}